// round 7
// baseline (speedup 1.0000x reference)
#include <cuda_runtime.h>

// PointPillarScatter: out[b,c,yi,xi] = feat[b,c,n*] where n* = max point index
// mapping to cell (yi,xi) in batch b (JAX scatter-set last-wins); 0 elsewhere.
// Index math replicates XLA: /0.16f -> *fp32(1/0.16f) == *6.25f exactly.
//
// 8-channel interleave: row8[g8][n][8ch] (32B rows). Fill reads one cell's
// 32B as two adjacent LDG.128 (same L2 sector -> one fully-used LTS transfer),
// halving gather LTS bytes vs 16B rows. Output stores use __stcs to keep the
// scratch L2-resident.

namespace {
constexpr int B  = 4;
constexpr int C  = 64;
constexpr int N  = 100000;
constexpr int NY = 496;
constexpr int NX = 432;
constexpr int CELLS  = NY * NX;      // 214272
constexpr int VCELLS = CELLS / 4;    // 53568 (float4 granularity)
constexpr int HV     = VCELLS / 2;   // 26784 (split-half stride, cell-quads)
constexpr int G8     = B * (C / 8);  // 32 8-channel groups
constexpr int HP2    = N / 2;        // 50000 (split-half stride, points)
}

// Scratch (no runtime allocation allowed).
__device__ __align__(16) int   g_winner[B * CELLS];
__device__ float g_minxy[B][2];
__device__ __align__(16) float g_row8[(size_t)G8 * N * 8];   // 102.4 MB

__device__ __forceinline__ void atomicMinF(float* addr, float v) {
    if (v >= 0.0f) atomicMin((int*)addr, __float_as_int(v));
    else           atomicMax((unsigned int*)addr, __float_as_uint(v));
}

__global__ void pp_init() {
    int i = blockIdx.x * blockDim.x + threadIdx.x;
    if (i < B * VCELLS) reinterpret_cast<int4*>(g_winner)[i] = make_int4(-1, -1, -1, -1);
    if (i < B * 2) reinterpret_cast<float*>(g_minxy)[i] = __int_as_float(0x7f800000);
}

// Per-batch min over x,y. points row = [b, x, y, z] as float4.
__global__ void pp_min(const float4* __restrict__ pts) {
    const int b = blockIdx.y;
    const float INF = __int_as_float(0x7f800000);
    float mx = INF, my = INF;
    for (int n = blockIdx.x * blockDim.x + threadIdx.x; n < N; n += gridDim.x * blockDim.x) {
        float4 v = pts[b * N + n];
        mx = fminf(mx, v.y);
        my = fminf(my, v.z);
    }
    #pragma unroll
    for (int o = 16; o; o >>= 1) {
        mx = fminf(mx, __shfl_xor_sync(0xffffffffu, mx, o));
        my = fminf(my, __shfl_xor_sync(0xffffffffu, my, o));
    }
    __shared__ float sx[32], sy[32];
    const int warp = threadIdx.x >> 5, lane = threadIdx.x & 31;
    if (lane == 0) { sx[warp] = mx; sy[warp] = my; }
    __syncthreads();
    if (warp == 0) {
        const int nw = blockDim.x >> 5;
        mx = (lane < nw) ? sx[lane] : INF;
        my = (lane < nw) ? sy[lane] : INF;
        #pragma unroll
        for (int o = 16; o; o >>= 1) {
            mx = fminf(mx, __shfl_xor_sync(0xffffffffu, mx, o));
            my = fminf(my, __shfl_xor_sync(0xffffffffu, my, o));
        }
        if (lane == 0) {
            atomicMinF(&g_minxy[b][0], mx);
            atomicMinF(&g_minxy[b][1], my);
        }
    }
}

// Elect per-cell winner = max point index (JAX scatter-set last-wins).
__global__ void pp_winner(const float4* __restrict__ pts) {
    const int b = blockIdx.y;
    const float xmin = g_minxy[b][0];
    const float ymin = g_minxy[b][1];
    const int n = blockIdx.x * blockDim.x + threadIdx.x;
    if (n >= N) return;
    float4 v = pts[b * N + n];
    const float R = 6.25f;                 // fp32(1/0.16f) == 6.25f (XLA rewrite)
    int xi = (int)floorf((v.y - xmin) * R);
    int yi = (int)floorf((v.z - ymin) * R);
    xi = min(max(xi, 0), NX - 1);
    yi = min(max(yi, 0), NY - 1);
    atomicMax(&g_winner[b * CELLS + yi * NX + xi], n);
}

// Transpose to 32B rows: row8[g8][n][k] = feat[plane g8*8+k][n].
// One point per thread (x2 split-half ILP). Loads: 8 coalesced 4B streams.
// Stores: 2x STG.128 at 32B lane stride (4 lanes per 128B line).
__global__ void __launch_bounds__(256) pp_transpose8(const float* __restrict__ feat) {
    int idx = blockIdx.x * blockDim.x + threadIdx.x;    // over G8 * HP2
    if (idx >= G8 * HP2) return;
    const int n  = idx % HP2;
    const int g8 = idx / HP2;
    const float* fin = feat + (size_t)g8 * 8 * N;       // 8 channel planes
    float v[2][8];
    #pragma unroll
    for (int j = 0; j < 2; ++j) {
        const int nn = n + j * HP2;
        #pragma unroll
        for (int k = 0; k < 8; ++k)
            v[j][k] = __ldg(fin + (size_t)k * N + nn);
    }
    float4* o = reinterpret_cast<float4*>(g_row8) + (size_t)g8 * N * 2;
    #pragma unroll
    for (int j = 0; j < 2; ++j) {
        const int nn = n + j * HP2;
        o[nn * 2 + 0] = make_float4(v[j][0], v[j][1], v[j][2], v[j][3]);
        o[nn * 2 + 1] = make_float4(v[j][4], v[j][5], v[j][6], v[j][7]);
    }
}

// Fill: per thread = (group g8, cell-quads h and h+HV). Each cell's 8-channel
// row is 32B = two adjacent LDG.128 (one L2 sector). Stores: 16 coalesced
// streaming STG.128 (8 channel planes x 2 halves).
__global__ void __launch_bounds__(256) pp_fill8(float4* __restrict__ out) {
    const int total = G8 * HV;
    int idx = blockIdx.x * blockDim.x + threadIdx.x;
    if (idx >= total) return;
    const int h  = idx % HV;
    const int g8 = idx / HV;
    const int b  = g8 >> 3;
    const int4* wp = reinterpret_cast<const int4*>(g_winner) + b * VCELLS;
    int4 w0 = wp[h];
    int4 w1 = wp[h + HV];
    const float4* fp = reinterpret_cast<const float4*>(g_row8) + (size_t)g8 * N * 2;
    const float4 z = make_float4(0.f, 0.f, 0.f, 0.f);
    float4 lo[8], hi[8];
    int wn[8] = {w0.x, w0.y, w0.z, w0.w, w1.x, w1.y, w1.z, w1.w};
    #pragma unroll
    for (int i = 0; i < 8; ++i) {
        lo[i] = (wn[i] >= 0) ? __ldg(fp + 2 * wn[i])     : z;
        hi[i] = (wn[i] >= 0) ? __ldg(fp + 2 * wn[i] + 1) : z;
    }
    float4* ob = out + (size_t)g8 * 8 * VCELLS;
    #pragma unroll
    for (int k = 0; k < 4; ++k) {
        float4 s0, s1;
        s0 = make_float4(((const float*)&lo[0])[k], ((const float*)&lo[1])[k],
                         ((const float*)&lo[2])[k], ((const float*)&lo[3])[k]);
        s1 = make_float4(((const float*)&lo[4])[k], ((const float*)&lo[5])[k],
                         ((const float*)&lo[6])[k], ((const float*)&lo[7])[k]);
        __stcs(ob + (size_t)k * VCELLS + h,      s0);
        __stcs(ob + (size_t)k * VCELLS + h + HV, s1);
        s0 = make_float4(((const float*)&hi[0])[k], ((const float*)&hi[1])[k],
                         ((const float*)&hi[2])[k], ((const float*)&hi[3])[k]);
        s1 = make_float4(((const float*)&hi[4])[k], ((const float*)&hi[5])[k],
                         ((const float*)&hi[6])[k], ((const float*)&hi[7])[k]);
        __stcs(ob + (size_t)(k + 4) * VCELLS + h,      s0);
        __stcs(ob + (size_t)(k + 4) * VCELLS + h + HV, s1);
    }
}

extern "C" void kernel_launch(void* const* d_in, const int* in_sizes, int n_in,
                              void* d_out, int out_size) {
    (void)in_sizes; (void)n_in; (void)out_size;
    const float*  feat = (const float*)d_in[0];   // (B, C, N) f32
    const float4* pts  = (const float4*)d_in[1];  // (B*N, 4)  f32
    // d_in[2] (voxel_coords) unused by the reference computation.

    pp_init<<<(B * VCELLS + 255) / 256, 256>>>();
    pp_min<<<dim3(98, B), 256>>>(pts);
    pp_winner<<<dim3((N + 255) / 256, B), 256>>>(pts);
    pp_transpose8<<<(G8 * HP2 + 255) / 256, 256>>>(feat);
    pp_fill8<<<(G8 * HV + 255) / 256, 256>>>((float4*)d_out);
}

// round 8
// speedup vs baseline: 1.0168x; 1.0168x over previous
#include <cuda_runtime.h>

// PointPillarScatter: out[b,c,yi,xi] = feat[b,c,n*] where n* = max point index
// mapping to cell (yi,xi) in batch b (JAX scatter-set last-wins); 0 elsewhere.
// Index math replicates XLA: /0.16f -> *fp32(1/0.16f) == *6.25f exactly.
//
// DRAM-byte-reduction round:
//  - scratch row8[g8][n][8ch] kept L2-resident: feat read with __ldcs
//    (evict-first), output written with __stcs; scratch default policy.
//  - pp_mark flags winner points; transpose skips stores for dead points
//    (~20% fewer scratch writes, smaller resident footprint).

namespace {
constexpr int B  = 4;
constexpr int C  = 64;
constexpr int N  = 100000;
constexpr int NY = 496;
constexpr int NX = 432;
constexpr int CELLS  = NY * NX;      // 214272
constexpr int VCELLS = CELLS / 4;    // 53568 (float4 granularity)
constexpr int HV     = VCELLS / 2;   // 26784 (split-half stride, cell-quads)
constexpr int G8     = B * (C / 8);  // 32 8-channel groups
constexpr int HP2    = N / 2;        // 50000 (split-half stride, points)
}

// Scratch (no runtime allocation allowed).
__device__ __align__(16) int   g_winner[B * CELLS];
__device__ float g_minxy[B][2];
__device__ unsigned char g_keep[B * N];                       // winner-point flag
__device__ __align__(16) float g_row8[(size_t)G8 * N * 8];    // 102.4 MB

__device__ __forceinline__ void atomicMinF(float* addr, float v) {
    if (v >= 0.0f) atomicMin((int*)addr, __float_as_int(v));
    else           atomicMax((unsigned int*)addr, __float_as_uint(v));
}

__global__ void pp_init() {
    int i = blockIdx.x * blockDim.x + threadIdx.x;
    if (i < B * VCELLS) reinterpret_cast<int4*>(g_winner)[i] = make_int4(-1, -1, -1, -1);
    if (i < B * 2) reinterpret_cast<float*>(g_minxy)[i] = __int_as_float(0x7f800000);
}

// Per-batch min over x,y. points row = [b, x, y, z] as float4.
__global__ void pp_min(const float4* __restrict__ pts) {
    const int b = blockIdx.y;
    const float INF = __int_as_float(0x7f800000);
    float mx = INF, my = INF;
    for (int n = blockIdx.x * blockDim.x + threadIdx.x; n < N; n += gridDim.x * blockDim.x) {
        float4 v = pts[b * N + n];
        mx = fminf(mx, v.y);
        my = fminf(my, v.z);
    }
    #pragma unroll
    for (int o = 16; o; o >>= 1) {
        mx = fminf(mx, __shfl_xor_sync(0xffffffffu, mx, o));
        my = fminf(my, __shfl_xor_sync(0xffffffffu, my, o));
    }
    __shared__ float sx[32], sy[32];
    const int warp = threadIdx.x >> 5, lane = threadIdx.x & 31;
    if (lane == 0) { sx[warp] = mx; sy[warp] = my; }
    __syncthreads();
    if (warp == 0) {
        const int nw = blockDim.x >> 5;
        mx = (lane < nw) ? sx[lane] : INF;
        my = (lane < nw) ? sy[lane] : INF;
        #pragma unroll
        for (int o = 16; o; o >>= 1) {
            mx = fminf(mx, __shfl_xor_sync(0xffffffffu, mx, o));
            my = fminf(my, __shfl_xor_sync(0xffffffffu, my, o));
        }
        if (lane == 0) {
            atomicMinF(&g_minxy[b][0], mx);
            atomicMinF(&g_minxy[b][1], my);
        }
    }
}

__device__ __forceinline__ int cell_of(const float4& v, float xmin, float ymin) {
    const float R = 6.25f;                 // fp32(1/0.16f) == 6.25f (XLA rewrite)
    int xi = (int)floorf((v.y - xmin) * R);
    int yi = (int)floorf((v.z - ymin) * R);
    xi = min(max(xi, 0), NX - 1);
    yi = min(max(yi, 0), NY - 1);
    return yi * NX + xi;
}

// Elect per-cell winner = max point index (JAX scatter-set last-wins).
__global__ void pp_winner(const float4* __restrict__ pts) {
    const int b = blockIdx.y;
    const int n = blockIdx.x * blockDim.x + threadIdx.x;
    if (n >= N) return;
    float4 v = pts[b * N + n];
    atomicMax(&g_winner[b * CELLS + cell_of(v, g_minxy[b][0], g_minxy[b][1])], n);
}

// Flag points that won their cell (the only rows fill will ever gather).
__global__ void pp_mark(const float4* __restrict__ pts) {
    const int b = blockIdx.y;
    const int n = blockIdx.x * blockDim.x + threadIdx.x;
    if (n >= N) return;
    float4 v = pts[b * N + n];
    int cell = cell_of(v, g_minxy[b][0], g_minxy[b][1]);
    g_keep[b * N + n] = (g_winner[b * CELLS + cell] == n) ? 1 : 0;
}

// Transpose to 32B rows: row8[g8][n][k] = feat[plane g8*8+k][n], winner rows
// only. feat streamed with __ldcs so scratch stays L2-resident.
__global__ void __launch_bounds__(256) pp_transpose8(const float* __restrict__ feat) {
    int idx = blockIdx.x * blockDim.x + threadIdx.x;    // over G8 * HP2
    if (idx >= G8 * HP2) return;
    const int n  = idx % HP2;
    const int g8 = idx / HP2;
    const int b  = g8 >> 3;
    const float* fin = feat + (size_t)g8 * 8 * N;       // 8 channel planes
    float4* o = reinterpret_cast<float4*>(g_row8) + (size_t)g8 * N * 2;
    #pragma unroll
    for (int j = 0; j < 2; ++j) {
        const int nn = n + j * HP2;
        float v[8];
        #pragma unroll
        for (int k = 0; k < 8; ++k)
            v[k] = __ldcs(fin + (size_t)k * N + nn);
        if (g_keep[b * N + nn]) {
            o[nn * 2 + 0] = make_float4(v[0], v[1], v[2], v[3]);
            o[nn * 2 + 1] = make_float4(v[4], v[5], v[6], v[7]);
        }
    }
}

// Fill: per thread = (group g8, cell-quads h and h+HV). Each cell's 8-channel
// row = two adjacent LDG.128 (default policy: hits L2-resident scratch).
// Stores: 16 coalesced streaming STG.128.
__global__ void __launch_bounds__(256) pp_fill8(float4* __restrict__ out) {
    const int total = G8 * HV;
    int idx = blockIdx.x * blockDim.x + threadIdx.x;
    if (idx >= total) return;
    const int h  = idx % HV;
    const int g8 = idx / HV;
    const int b  = g8 >> 3;
    const int4* wp = reinterpret_cast<const int4*>(g_winner) + b * VCELLS;
    int4 w0 = wp[h];
    int4 w1 = wp[h + HV];
    const float4* fp = reinterpret_cast<const float4*>(g_row8) + (size_t)g8 * N * 2;
    const float4 z = make_float4(0.f, 0.f, 0.f, 0.f);
    float4 lo[8], hi[8];
    int wn[8] = {w0.x, w0.y, w0.z, w0.w, w1.x, w1.y, w1.z, w1.w};
    #pragma unroll
    for (int i = 0; i < 8; ++i) {
        lo[i] = (wn[i] >= 0) ? __ldg(fp + 2 * wn[i])     : z;
        hi[i] = (wn[i] >= 0) ? __ldg(fp + 2 * wn[i] + 1) : z;
    }
    float4* ob = out + (size_t)g8 * 8 * VCELLS;
    #pragma unroll
    for (int k = 0; k < 4; ++k) {
        float4 s0, s1;
        s0 = make_float4(((const float*)&lo[0])[k], ((const float*)&lo[1])[k],
                         ((const float*)&lo[2])[k], ((const float*)&lo[3])[k]);
        s1 = make_float4(((const float*)&lo[4])[k], ((const float*)&lo[5])[k],
                         ((const float*)&lo[6])[k], ((const float*)&lo[7])[k]);
        __stcs(ob + (size_t)k * VCELLS + h,      s0);
        __stcs(ob + (size_t)k * VCELLS + h + HV, s1);
        s0 = make_float4(((const float*)&hi[0])[k], ((const float*)&hi[1])[k],
                         ((const float*)&hi[2])[k], ((const float*)&hi[3])[k]);
        s1 = make_float4(((const float*)&hi[4])[k], ((const float*)&hi[5])[k],
                         ((const float*)&hi[6])[k], ((const float*)&hi[7])[k]);
        __stcs(ob + (size_t)(k + 4) * VCELLS + h,      s0);
        __stcs(ob + (size_t)(k + 4) * VCELLS + h + HV, s1);
    }
}

extern "C" void kernel_launch(void* const* d_in, const int* in_sizes, int n_in,
                              void* d_out, int out_size) {
    (void)in_sizes; (void)n_in; (void)out_size;
    const float*  feat = (const float*)d_in[0];   // (B, C, N) f32
    const float4* pts  = (const float4*)d_in[1];  // (B*N, 4)  f32
    // d_in[2] (voxel_coords) unused by the reference computation.

    pp_init<<<(B * VCELLS + 255) / 256, 256>>>();
    pp_min<<<dim3(98, B), 256>>>(pts);
    pp_winner<<<dim3((N + 255) / 256, B), 256>>>(pts);
    pp_mark<<<dim3((N + 255) / 256, B), 256>>>(pts);
    pp_transpose8<<<(G8 * HP2 + 255) / 256, 256>>>(feat);
    pp_fill8<<<(G8 * HV + 255) / 256, 256>>>((float4*)d_out);
}